// round 2
// baseline (speedup 1.0000x reference)
#include <cuda_runtime.h>
#include <math.h>

// Model dims
#define BB   2
#define TT   1024
#define DD   1024
#define HH   16
#define HDIM 64
#define LL   8
#define VV   32000
#define MM   (BB*TT)   // 2048 tokens
#define QB   8         // queries per attention block

// Scratch (device globals; no allocation allowed)
__device__ float g_x  [MM * DD];        // residual stream
__device__ float g_h  [MM * DD];        // layernorm output
__device__ float g_qkv[MM * 3 * DD];    // qkv projections
__device__ float g_y  [MM * DD];        // attention output
__device__ float g_g  [MM * 4 * DD];    // MLP hidden

// ---------------------------------------------------------------------------
// Embedding: x[token] = wte[idx[token]] + wpe[t]
// ---------------------------------------------------------------------------
__global__ void embed_kernel(const int* __restrict__ idx,
                             const float* __restrict__ wte,
                             const float* __restrict__ wpe,
                             float* __restrict__ x) {
    int token = blockIdx.x;
    int t = token % TT;
    int id = idx[token];
    const float4* src = (const float4*)(wte + (size_t)id * DD);
    const float4* pos = (const float4*)(wpe + (size_t)t * DD);
    float4* dst = (float4*)(x + (size_t)token * DD);
    for (int i = threadIdx.x; i < DD / 4; i += blockDim.x) {
        float4 a = src[i], b = pos[i];
        dst[i] = make_float4(a.x + b.x, a.y + b.y, a.z + b.z, a.w + b.w);
    }
}

// ---------------------------------------------------------------------------
// LayerNorm over D=1024. One block (256 threads) per token; float4 per thread.
// ---------------------------------------------------------------------------
__global__ __launch_bounds__(256) void ln_kernel(const float* __restrict__ x,
                                                 const float* __restrict__ sc,
                                                 const float* __restrict__ bi,
                                                 float* __restrict__ out) {
    int token = blockIdx.x;
    const float4* xp = (const float4*)(x + (size_t)token * DD);
    float4 v = xp[threadIdx.x];
    float s = v.x + v.y + v.z + v.w;
    float q = v.x * v.x + v.y * v.y + v.z * v.z + v.w * v.w;
#pragma unroll
    for (int o = 16; o; o >>= 1) {
        s += __shfl_xor_sync(0xffffffffu, s, o);
        q += __shfl_xor_sync(0xffffffffu, q, o);
    }
    __shared__ float ss[8], sq[8];
    int w = threadIdx.x >> 5, l = threadIdx.x & 31;
    if (l == 0) { ss[w] = s; sq[w] = q; }
    __syncthreads();
    if (w == 0) {
        s = (l < 8) ? ss[l] : 0.f;
        q = (l < 8) ? sq[l] : 0.f;
#pragma unroll
        for (int o = 4; o; o >>= 1) {
            s += __shfl_xor_sync(0xffffffffu, s, o);
            q += __shfl_xor_sync(0xffffffffu, q, o);
        }
        if (l == 0) { ss[0] = s; sq[0] = q; }
    }
    __syncthreads();
    float mu  = ss[0] * (1.f / DD);
    float var = sq[0] * (1.f / DD) - mu * mu;
    float inv = rsqrtf(var + 1e-5f);
    float4 sv = ((const float4*)sc)[threadIdx.x];
    float4 bv = ((const float4*)bi)[threadIdx.x];
    float4 r;
    r.x = (v.x - mu) * inv * sv.x + bv.x;
    r.y = (v.y - mu) * inv * sv.y + bv.y;
    r.z = (v.z - mu) * inv * sv.z + bv.z;
    r.w = (v.w - mu) * inv * sv.w + bv.w;
    ((float4*)(out + (size_t)token * DD))[threadIdx.x] = r;
}

// ---------------------------------------------------------------------------
// SGEMM NT: C[m,n] = sum_k A[m,k] * B[n,k]  (both K-contiguous, row-major)
// 128x128 tile, BK=8, 256 threads, 8x8 per thread. All dims divide tiles.
// flags: 1=add bias[n], 2=add res[m,n], 4=exact GELU. C may alias res.
// ---------------------------------------------------------------------------
#define FLAG_BIAS 1
#define FLAG_RES  2
#define FLAG_GELU 4

__device__ __forceinline__ float gelu_exact(float v) {
    return 0.5f * v * (1.f + erff(v * 0.70710678118654752f));
}

__global__ __launch_bounds__(256) void sgemm_nt(const float* __restrict__ A,
                                                const float* __restrict__ B,
                                                const float* __restrict__ bias,
                                                const float* res,
                                                float* C,
                                                int M, int N, int K, int flags) {
    __shared__ __align__(16) float As[8][128];
    __shared__ __align__(16) float Bs[8][128];
    int tid = threadIdx.x;
    int bm = blockIdx.y * 128;
    int bn = blockIdx.x * 128;

    int lrow = tid >> 1;           // 0..127
    int lcol = (tid & 1) * 4;      // 0 or 4
    const float* Aload = A + (size_t)(bm + lrow) * K + lcol;
    const float* Bload = B + (size_t)(bn + lrow) * K + lcol;

    int tx = tid & 15;             // 0..15 -> n
    int ty = tid >> 4;             // 0..15 -> m
    float acc[8][8];
#pragma unroll
    for (int i = 0; i < 8; i++)
#pragma unroll
        for (int j = 0; j < 8; j++) acc[i][j] = 0.f;

    for (int k0 = 0; k0 < K; k0 += 8) {
        float4 a4 = *(const float4*)(Aload + k0);
        float4 b4 = *(const float4*)(Bload + k0);
        __syncthreads();
        As[lcol + 0][lrow] = a4.x; As[lcol + 1][lrow] = a4.y;
        As[lcol + 2][lrow] = a4.z; As[lcol + 3][lrow] = a4.w;
        Bs[lcol + 0][lrow] = b4.x; Bs[lcol + 1][lrow] = b4.y;
        Bs[lcol + 2][lrow] = b4.z; Bs[lcol + 3][lrow] = b4.w;
        __syncthreads();
#pragma unroll
        for (int kk = 0; kk < 8; kk++) {
            float ar[8], br[8];
            *(float4*)(ar)     = *(const float4*)&As[kk][ty * 8];
            *(float4*)(ar + 4) = *(const float4*)&As[kk][ty * 8 + 4];
            *(float4*)(br)     = *(const float4*)&Bs[kk][tx * 8];
            *(float4*)(br + 4) = *(const float4*)&Bs[kk][tx * 8 + 4];
#pragma unroll
            for (int i = 0; i < 8; i++)
#pragma unroll
                for (int j = 0; j < 8; j++)
                    acc[i][j] = fmaf(ar[i], br[j], acc[i][j]);
        }
    }

    float bv[8];
    if (flags & FLAG_BIAS) {
#pragma unroll
        for (int j = 0; j < 8; j++) bv[j] = bias[bn + tx * 8 + j];
    }
#pragma unroll
    for (int i = 0; i < 8; i++) {
        int m = bm + ty * 8 + i;
        float* crow = C + (size_t)m * N + bn + tx * 8;
        const float* rrow = (flags & FLAG_RES) ? (res + (size_t)m * N + bn + tx * 8) : nullptr;
#pragma unroll
        for (int j = 0; j < 8; j += 4) {
            float4 o;
            o.x = acc[i][j + 0]; o.y = acc[i][j + 1];
            o.z = acc[i][j + 2]; o.w = acc[i][j + 3];
            if (flags & FLAG_BIAS) { o.x += bv[j]; o.y += bv[j + 1]; o.z += bv[j + 2]; o.w += bv[j + 3]; }
            if (flags & FLAG_GELU) {
                o.x = gelu_exact(o.x); o.y = gelu_exact(o.y);
                o.z = gelu_exact(o.z); o.w = gelu_exact(o.w);
            }
            if (flags & FLAG_RES) {
                float4 r = *(const float4*)(rrow + j);
                o.x += r.x; o.y += r.y; o.z += r.z; o.w += r.w;
            }
            *(float4*)(crow + j) = o;
        }
    }
}

// ---------------------------------------------------------------------------
// Full CAUSAL attention (flash-style, online softmax), HD=64.
// Grid: (T/QB, H, B). 8 warps/block, one query per warp. K/V tiles of 32 keys
// staged in smem; per-lane-per-key scores; PV via p buffer in smem.
// qkv layout: [token][3*D] with q|k|v contiguous per token.
// ---------------------------------------------------------------------------
__global__ __launch_bounds__(QB * 32) void attn_kernel(const float* __restrict__ qkv,
                                                       float* __restrict__ y) {
    int b = blockIdx.z, h = blockIdx.y;
    int warp = threadIdx.x >> 5, lane = threadIdx.x & 31;
    int tid = threadIdx.x;
    int t = blockIdx.x * QB + warp;             // this warp's query index
    int token = b * TT + t;

    __shared__ float q_s[QB][66];
    __shared__ float k_s[32][66];
    __shared__ float v_s[32][66];
    __shared__ float p_s[QB][32];

    // load q row for this warp (float2 per lane)
    {
        const float* qp = qkv + (size_t)token * (3 * DD) + h * HDIM;
        float2 qv = *(const float2*)(qp + lane * 2);
        *(float2*)&q_s[warp][lane * 2] = qv;
    }

    float m = -INFINITY, l = 0.f;
    float2 acc = make_float2(0.f, 0.f);

    int t_max = blockIdx.x * QB + (QB - 1);     // last query in block
    int ntiles = t_max / 32 + 1;

    const float* kbase = qkv + (size_t)(b * TT) * (3 * DD) + DD + h * HDIM;
    const float* vbase = kbase + DD;

    for (int tile = 0; tile < ntiles; tile++) {
        int kt = tile * 32;
        __syncthreads();  // protect previous tile's smem reads
        // cooperative load of K,V tile: 32 rows x 32 float2 each
#pragma unroll
        for (int i = tid; i < 32 * 32; i += QB * 32) {
            int r = i >> 5, c = i & 31;
            const float* krow = kbase + (size_t)(kt + r) * (3 * DD);
            const float* vrow = vbase + (size_t)(kt + r) * (3 * DD);
            *(float2*)&k_s[r][c * 2] = *(const float2*)(krow + c * 2);
            *(float2*)&v_s[r][c * 2] = *(const float2*)(vrow + c * 2);
        }
        __syncthreads();

        if (kt <= t) {
            int key = kt + lane;
            float s = -INFINITY;
            if (key <= t) {
                const float2* krow = (const float2*)&k_s[lane][0];
                const float2* qrow = (const float2*)&q_s[warp][0];
                float s0 = 0.f;
#pragma unroll
                for (int d = 0; d < 32; d++) {
                    float2 kk = krow[d];
                    float2 qq = qrow[d];
                    s0 = fmaf(qq.x, kk.x, s0);
                    s0 = fmaf(qq.y, kk.y, s0);
                }
                s = s0 * 0.125f;   // 1/sqrt(64)
            }
            // warp max of scores
            float tm = s;
#pragma unroll
            for (int o = 16; o; o >>= 1) tm = fmaxf(tm, __shfl_xor_sync(0xffffffffu, tm, o));
            float m_new = fmaxf(m, tm);
            float corr = expf(m - m_new);       // 0 on first tile (m=-inf, m_new finite)
            float p = (key <= t) ? expf(s - m_new) : 0.f;
            float psum = p;
#pragma unroll
            for (int o = 16; o; o >>= 1) psum += __shfl_xor_sync(0xffffffffu, psum, o);
            l = l * corr + psum;
            acc.x *= corr; acc.y *= corr;
            m = m_new;

            p_s[warp][lane] = p;
            __syncwarp();
#pragma unroll
            for (int j = 0; j < 32; j++) {
                float pj = p_s[warp][j];
                float2 vv = *(const float2*)&v_s[j][lane * 2];
                acc.x = fmaf(pj, vv.x, acc.x);
                acc.y = fmaf(pj, vv.y, acc.y);
            }
        }
    }

    float inv = 1.f / l;
    float* yp = y + (size_t)token * DD + h * HDIM;
    *(float2*)(yp + lane * 2) = make_float2(acc.x * inv, acc.y * inv);
}

// ---------------------------------------------------------------------------
// Host launcher
// ---------------------------------------------------------------------------
extern "C" void kernel_launch(void* const* d_in, const int* in_sizes, int n_in,
                              void* d_out, int out_size) {
    const int*   idx    = (const int*)  d_in[0];
    const float* wte    = (const float*)d_in[1];
    const float* wpe    = (const float*)d_in[2];
    const float* ln1_s  = (const float*)d_in[3];
    const float* ln1_b  = (const float*)d_in[4];
    const float* qkv_w  = (const float*)d_in[5];
    const float* proj_w = (const float*)d_in[6];
    const float* ln2_s  = (const float*)d_in[7];
    const float* ln2_b  = (const float*)d_in[8];
    const float* fc_w   = (const float*)d_in[9];
    const float* fc_b   = (const float*)d_in[10];
    const float* fc2_w  = (const float*)d_in[11];
    const float* fc2_b  = (const float*)d_in[12];
    const float* lnf_s  = (const float*)d_in[13];
    const float* lnf_b  = (const float*)d_in[14];
    const float* lm_w   = (const float*)d_in[15];
    float* out = (float*)d_out;

    float *x, *h, *qkv, *y, *g;
    cudaGetSymbolAddress((void**)&x,   g_x);
    cudaGetSymbolAddress((void**)&h,   g_h);
    cudaGetSymbolAddress((void**)&qkv, g_qkv);
    cudaGetSymbolAddress((void**)&y,   g_y);
    cudaGetSymbolAddress((void**)&g,   g_g);

    embed_kernel<<<MM, 256>>>(idx, wte, wpe, x);

    for (int l = 0; l < LL; l++) {
        const float* qw  = qkv_w  + (size_t)l * 3 * DD * DD;
        const float* pw  = proj_w + (size_t)l * DD * DD;
        const float* fw  = fc_w   + (size_t)l * 4 * DD * DD;
        const float* fb  = fc_b   + (size_t)l * 4 * DD;
        const float* f2w = fc2_w  + (size_t)l * DD * 4 * DD;
        const float* f2b = fc2_b  + (size_t)l * DD;

        // h = LN1(x)
        ln_kernel<<<MM, 256>>>(x, ln1_s + l * DD, ln1_b + l * DD, h);
        // qkv = h @ qkv_w^T         [2048 x 3072], K=1024
        sgemm_nt<<<dim3(3 * DD / 128, MM / 128), 256>>>(h, qw, nullptr, nullptr, qkv,
                                                        MM, 3 * DD, DD, 0);
        // y = causal attention
        attn_kernel<<<dim3(TT / QB, HH, BB), QB * 32>>>(qkv, y);
        // x = x + y @ proj_w^T      [2048 x 1024], K=1024
        sgemm_nt<<<dim3(DD / 128, MM / 128), 256>>>(y, pw, nullptr, x, x,
                                                    MM, DD, DD, FLAG_RES);
        // h = LN2(x)
        ln_kernel<<<MM, 256>>>(x, ln2_s + l * DD, ln2_b + l * DD, h);
        // g = gelu(h @ fc_w^T + fc_b)   [2048 x 4096], K=1024
        sgemm_nt<<<dim3(4 * DD / 128, MM / 128), 256>>>(h, fw, fb, nullptr, g,
                                                        MM, 4 * DD, DD, FLAG_BIAS | FLAG_GELU);
        // x = x + g @ fc2_w^T + fc2_b   [2048 x 1024], K=4096
        sgemm_nt<<<dim3(DD / 128, MM / 128), 256>>>(g, f2w, f2b, x, x,
                                                    MM, DD, 4 * DD, FLAG_BIAS | FLAG_RES);
    }

    // h = LNf(x)
    ln_kernel<<<MM, 256>>>(x, lnf_s, lnf_b, h);
    // out = h @ lm_w^T   [2048 x 32000], K=1024
    sgemm_nt<<<dim3(VV / 128, MM / 128), 256>>>(h, lm_w, nullptr, nullptr, out,
                                                MM, VV, DD, 0);
}

// round 3
// speedup vs baseline: 2.2396x; 2.2396x over previous
#include <cuda_runtime.h>
#include <cuda_bf16.h>
#include <math.h>
#include <stdint.h>

// Model dims
#define BB   2
#define TT   1024
#define DD   1024
#define HH   16
#define HDIM 64
#define LL   8
#define VV   32000
#define MM   (BB*TT)   // 2048 tokens
#define QB   8         // queries per attention block

// GEMM tiling
#define BM 128
#define BN 128
#define BK 32
#define LDP 40         // smem row stride in bf16 elements (pad 32 -> 40)

// Scratch (device globals; no allocation allowed)
__device__ float g_x  [MM * DD];
__device__ float g_h  [MM * DD];
__device__ float g_qkv[MM * 3 * DD];
__device__ float g_y  [MM * DD];
__device__ float g_g  [MM * 4 * DD];

// ---------------------------------------------------------------------------
// Embedding
// ---------------------------------------------------------------------------
__global__ void embed_kernel(const int* __restrict__ idx,
                             const float* __restrict__ wte,
                             const float* __restrict__ wpe,
                             float* __restrict__ x) {
    int token = blockIdx.x;
    int t = token % TT;
    int id = idx[token];
    const float4* src = (const float4*)(wte + (size_t)id * DD);
    const float4* pos = (const float4*)(wpe + (size_t)t * DD);
    float4* dst = (float4*)(x + (size_t)token * DD);
    for (int i = threadIdx.x; i < DD / 4; i += blockDim.x) {
        float4 a = src[i], b = pos[i];
        dst[i] = make_float4(a.x + b.x, a.y + b.y, a.z + b.z, a.w + b.w);
    }
}

// ---------------------------------------------------------------------------
// LayerNorm over D=1024
// ---------------------------------------------------------------------------
__global__ __launch_bounds__(256) void ln_kernel(const float* __restrict__ x,
                                                 const float* __restrict__ sc,
                                                 const float* __restrict__ bi,
                                                 float* __restrict__ out) {
    int token = blockIdx.x;
    const float4* xp = (const float4*)(x + (size_t)token * DD);
    float4 v = xp[threadIdx.x];
    float s = v.x + v.y + v.z + v.w;
    float q = v.x * v.x + v.y * v.y + v.z * v.z + v.w * v.w;
#pragma unroll
    for (int o = 16; o; o >>= 1) {
        s += __shfl_xor_sync(0xffffffffu, s, o);
        q += __shfl_xor_sync(0xffffffffu, q, o);
    }
    __shared__ float ss[8], sq[8];
    int w = threadIdx.x >> 5, l = threadIdx.x & 31;
    if (l == 0) { ss[w] = s; sq[w] = q; }
    __syncthreads();
    if (w == 0) {
        s = (l < 8) ? ss[l] : 0.f;
        q = (l < 8) ? sq[l] : 0.f;
#pragma unroll
        for (int o = 4; o; o >>= 1) {
            s += __shfl_xor_sync(0xffffffffu, s, o);
            q += __shfl_xor_sync(0xffffffffu, q, o);
        }
        if (l == 0) { ss[0] = s; sq[0] = q; }
    }
    __syncthreads();
    float mu  = ss[0] * (1.f / DD);
    float var = sq[0] * (1.f / DD) - mu * mu;
    float inv = rsqrtf(var + 1e-5f);
    float4 sv = ((const float4*)sc)[threadIdx.x];
    float4 bv = ((const float4*)bi)[threadIdx.x];
    float4 r;
    r.x = (v.x - mu) * inv * sv.x + bv.x;
    r.y = (v.y - mu) * inv * sv.y + bv.y;
    r.z = (v.z - mu) * inv * sv.z + bv.z;
    r.w = (v.w - mu) * inv * sv.w + bv.w;
    ((float4*)(out + (size_t)token * DD))[threadIdx.x] = r;
}

// ---------------------------------------------------------------------------
// Tensor-core GEMM NT with bf16-split emulation (3 mma passes = fp32-accurate)
// C[m,n] = sum_k A[m,k]*B[n,k]; 128x128 tile, BK=32, 8 warps (warp tile 64x32)
// ---------------------------------------------------------------------------
#define FLAG_BIAS 1
#define FLAG_RES  2
#define FLAG_GELU 4

__device__ __forceinline__ float gelu_exact(float v) {
    return 0.5f * v * (1.f + erff(v * 0.70710678118654752f));
}

__device__ __forceinline__ void ldm_x4(uint32_t& r0, uint32_t& r1, uint32_t& r2, uint32_t& r3,
                                       uint32_t addr) {
    asm volatile("ldmatrix.sync.aligned.m8n8.x4.shared.b16 {%0,%1,%2,%3}, [%4];\n"
                 : "=r"(r0), "=r"(r1), "=r"(r2), "=r"(r3) : "r"(addr));
}

__device__ __forceinline__ void mma16816(float* d, const uint32_t* a, const uint32_t* b) {
    asm volatile(
        "mma.sync.aligned.m16n8k16.row.col.f32.bf16.bf16.f32 "
        "{%0,%1,%2,%3}, {%4,%5,%6,%7}, {%8,%9}, {%0,%1,%2,%3};\n"
        : "+f"(d[0]), "+f"(d[1]), "+f"(d[2]), "+f"(d[3])
        : "r"(a[0]), "r"(a[1]), "r"(a[2]), "r"(a[3]), "r"(b[0]), "r"(b[1]));
}

__device__ __forceinline__ void split4(__nv_bfloat16* hi, __nv_bfloat16* lo, float4 v) {
    __nv_bfloat16 h0 = __float2bfloat16(v.x);
    __nv_bfloat16 h1 = __float2bfloat16(v.y);
    __nv_bfloat16 h2 = __float2bfloat16(v.z);
    __nv_bfloat16 h3 = __float2bfloat16(v.w);
    __nv_bfloat16 l0 = __float2bfloat16(v.x - __bfloat162float(h0));
    __nv_bfloat16 l1 = __float2bfloat16(v.y - __bfloat162float(h1));
    __nv_bfloat16 l2 = __float2bfloat16(v.z - __bfloat162float(h2));
    __nv_bfloat16 l3 = __float2bfloat16(v.w - __bfloat162float(h3));
    __nv_bfloat162 p;
    p.x = h0; p.y = h1; ((__nv_bfloat162*)hi)[0] = p;
    p.x = h2; p.y = h3; ((__nv_bfloat162*)hi)[1] = p;
    p.x = l0; p.y = l1; ((__nv_bfloat162*)lo)[0] = p;
    p.x = l2; p.y = l3; ((__nv_bfloat162*)lo)[1] = p;
}

__global__ __launch_bounds__(256, 1) void gemm_bf16s(const float* __restrict__ A,
                                                     const float* __restrict__ B,
                                                     const float* __restrict__ bias,
                                                     const float* res,
                                                     float* C,
                                                     int M, int N, int K, int flags) {
    __shared__ __align__(16) __nv_bfloat16 sm[4 * BM * LDP];
    __nv_bfloat16* Ah = sm;
    __nv_bfloat16* Al = sm + 1 * BM * LDP;
    __nv_bfloat16* Bh = sm + 2 * BM * LDP;
    __nv_bfloat16* Bl = sm + 3 * BM * LDP;

    int tid = threadIdx.x;
    int warp = tid >> 5, lane = tid & 31;
    int bm = blockIdx.y * BM, bn = blockIdx.x * BN;
    int wm = (warp >> 2) * 64;      // 0/64
    int wn = (warp & 3) * 32;       // 0/32/64/96

    float acc[4][4][4];
#pragma unroll
    for (int i = 0; i < 4; i++)
#pragma unroll
        for (int j = 0; j < 4; j++)
#pragma unroll
            for (int r = 0; r < 4; r++) acc[i][j][r] = 0.f;

    // ldmatrix lane addressing (non-transposed 8x8 fragments)
    int a_r = ((lane >> 3) & 1) * 8 + (lane & 7);  // row within frag pair
    int a_c = (lane >> 4) * 8;                     // k offset 0/8
    int b_r = (lane >> 4) * 8 + (lane & 7);        // n row within 16-row pair
    int b_c = ((lane >> 3) & 1) * 8;               // k offset 0/8

    uint32_t base = (uint32_t)__cvta_generic_to_shared(sm);
    const uint32_t offAh = 0;
    const uint32_t offAl = 1u * BM * LDP * 2;
    const uint32_t offBh = 2u * BM * LDP * 2;
    const uint32_t offBl = 3u * BM * LDP * 2;

    // prologue: load k0=0 tile into registers
    float4 a4[4], b4[4];
#pragma unroll
    for (int i = 0; i < 4; i++) {
        int idx = tid + i * 256;
        int row = idx >> 3, kc = (idx & 7) * 4;
        a4[i] = *(const float4*)(A + (size_t)(bm + row) * K + kc);
        b4[i] = *(const float4*)(B + (size_t)(bn + row) * K + kc);
    }

    for (int k0 = 0; k0 < K; k0 += BK) {
        __syncthreads();
#pragma unroll
        for (int i = 0; i < 4; i++) {
            int idx = tid + i * 256;
            int row = idx >> 3, kc = (idx & 7) * 4;
            split4(Ah + row * LDP + kc, Al + row * LDP + kc, a4[i]);
            split4(Bh + row * LDP + kc, Bl + row * LDP + kc, b4[i]);
        }
        __syncthreads();

        if (k0 + BK < K) {
#pragma unroll
            for (int i = 0; i < 4; i++) {
                int idx = tid + i * 256;
                int row = idx >> 3, kc = (idx & 7) * 4;
                a4[i] = *(const float4*)(A + (size_t)(bm + row) * K + k0 + BK + kc);
                b4[i] = *(const float4*)(B + (size_t)(bn + row) * K + k0 + BK + kc);
            }
        }

#pragma unroll
        for (int ks = 0; ks < BK; ks += 16) {
            uint32_t ah[4][4], al[4][4], bh[4][2], bl[4][2];
#pragma unroll
            for (int mf = 0; mf < 4; mf++) {
                uint32_t addr = base + offAh +
                    (uint32_t)((wm + mf * 16 + a_r) * LDP + ks + a_c) * 2;
                ldm_x4(ah[mf][0], ah[mf][1], ah[mf][2], ah[mf][3], addr);
            }
#pragma unroll
            for (int p = 0; p < 2; p++) {
                uint32_t addr = base + offBh +
                    (uint32_t)((wn + p * 16 + b_r) * LDP + ks + b_c) * 2;
                uint32_t r0, r1, r2, r3;
                ldm_x4(r0, r1, r2, r3, addr);
                bh[2 * p][0] = r0; bh[2 * p][1] = r1;
                bh[2 * p + 1][0] = r2; bh[2 * p + 1][1] = r3;
            }
#pragma unroll
            for (int mf = 0; mf < 4; mf++)
#pragma unroll
                for (int nf = 0; nf < 4; nf++)
                    mma16816(acc[mf][nf], ah[mf], bh[nf]);

#pragma unroll
            for (int p = 0; p < 2; p++) {
                uint32_t addr = base + offBl +
                    (uint32_t)((wn + p * 16 + b_r) * LDP + ks + b_c) * 2;
                uint32_t r0, r1, r2, r3;
                ldm_x4(r0, r1, r2, r3, addr);
                bl[2 * p][0] = r0; bl[2 * p][1] = r1;
                bl[2 * p + 1][0] = r2; bl[2 * p + 1][1] = r3;
            }
#pragma unroll
            for (int mf = 0; mf < 4; mf++)
#pragma unroll
                for (int nf = 0; nf < 4; nf++)
                    mma16816(acc[mf][nf], ah[mf], bl[nf]);

#pragma unroll
            for (int mf = 0; mf < 4; mf++) {
                uint32_t addr = base + offAl +
                    (uint32_t)((wm + mf * 16 + a_r) * LDP + ks + a_c) * 2;
                ldm_x4(al[mf][0], al[mf][1], al[mf][2], al[mf][3], addr);
            }
#pragma unroll
            for (int mf = 0; mf < 4; mf++)
#pragma unroll
                for (int nf = 0; nf < 4; nf++)
                    mma16816(acc[mf][nf], al[mf], bh[nf]);
        }
    }

    // epilogue: lane owns (row = groupID [+8], col = 2*tid4 pairs) per fragment
    int gid = lane >> 2, tg = lane & 3;
#pragma unroll
    for (int mf = 0; mf < 4; mf++) {
#pragma unroll
        for (int half = 0; half < 2; half++) {
            int row = bm + wm + mf * 16 + half * 8 + gid;
#pragma unroll
            for (int nf = 0; nf < 4; nf++) {
                int col = bn + wn + nf * 8 + tg * 2;
                float2 o;
                o.x = acc[mf][nf][half * 2 + 0];
                o.y = acc[mf][nf][half * 2 + 1];
                if (flags & FLAG_BIAS) { o.x += bias[col]; o.y += bias[col + 1]; }
                if (flags & FLAG_GELU) { o.x = gelu_exact(o.x); o.y = gelu_exact(o.y); }
                if (flags & FLAG_RES) {
                    float2 r = *(const float2*)(res + (size_t)row * N + col);
                    o.x += r.x; o.y += r.y;
                }
                *(float2*)(C + (size_t)row * N + col) = o;
            }
        }
    }
}

// ---------------------------------------------------------------------------
// Full CAUSAL attention (flash-style, online softmax), HD=64.
// ---------------------------------------------------------------------------
__global__ __launch_bounds__(QB * 32) void attn_kernel(const float* __restrict__ qkv,
                                                       float* __restrict__ y) {
    int b = blockIdx.z, h = blockIdx.y;
    int warp = threadIdx.x >> 5, lane = threadIdx.x & 31;
    int tid = threadIdx.x;
    int t = blockIdx.x * QB + warp;
    int token = b * TT + t;

    __shared__ float q_s[QB][66];
    __shared__ float k_s[32][66];
    __shared__ float v_s[32][66];
    __shared__ float p_s[QB][32];

    {
        const float* qp = qkv + (size_t)token * (3 * DD) + h * HDIM;
        float2 qv = *(const float2*)(qp + lane * 2);
        *(float2*)&q_s[warp][lane * 2] = qv;
    }

    float m = -INFINITY, l = 0.f;
    float2 acc = make_float2(0.f, 0.f);

    int t_max = blockIdx.x * QB + (QB - 1);
    int ntiles = t_max / 32 + 1;

    const float* kbase = qkv + (size_t)(b * TT) * (3 * DD) + DD + h * HDIM;
    const float* vbase = kbase + DD;

    for (int tile = 0; tile < ntiles; tile++) {
        int kt = tile * 32;
        __syncthreads();
#pragma unroll
        for (int i = tid; i < 32 * 32; i += QB * 32) {
            int r = i >> 5, c = i & 31;
            const float* krow = kbase + (size_t)(kt + r) * (3 * DD);
            const float* vrow = vbase + (size_t)(kt + r) * (3 * DD);
            *(float2*)&k_s[r][c * 2] = *(const float2*)(krow + c * 2);
            *(float2*)&v_s[r][c * 2] = *(const float2*)(vrow + c * 2);
        }
        __syncthreads();

        if (kt <= t) {
            int key = kt + lane;
            float s = -INFINITY;
            if (key <= t) {
                const float2* krow = (const float2*)&k_s[lane][0];
                const float2* qrow = (const float2*)&q_s[warp][0];
                float s0 = 0.f;
#pragma unroll
                for (int d = 0; d < 32; d++) {
                    float2 kk = krow[d];
                    float2 qq = qrow[d];
                    s0 = fmaf(qq.x, kk.x, s0);
                    s0 = fmaf(qq.y, kk.y, s0);
                }
                s = s0 * 0.125f;
            }
            float tm = s;
#pragma unroll
            for (int o = 16; o; o >>= 1) tm = fmaxf(tm, __shfl_xor_sync(0xffffffffu, tm, o));
            float m_new = fmaxf(m, tm);
            float corr = expf(m - m_new);
            float p = (key <= t) ? expf(s - m_new) : 0.f;
            float psum = p;
#pragma unroll
            for (int o = 16; o; o >>= 1) psum += __shfl_xor_sync(0xffffffffu, psum, o);
            l = l * corr + psum;
            acc.x *= corr; acc.y *= corr;
            m = m_new;

            p_s[warp][lane] = p;
            __syncwarp();
#pragma unroll
            for (int j = 0; j < 32; j++) {
                float pj = p_s[warp][j];
                float2 vv = *(const float2*)&v_s[j][lane * 2];
                acc.x = fmaf(pj, vv.x, acc.x);
                acc.y = fmaf(pj, vv.y, acc.y);
            }
        }
    }

    float inv = 1.f / l;
    float* yp = y + (size_t)token * DD + h * HDIM;
    *(float2*)(yp + lane * 2) = make_float2(acc.x * inv, acc.y * inv);
}

// ---------------------------------------------------------------------------
// Host launcher
// ---------------------------------------------------------------------------
extern "C" void kernel_launch(void* const* d_in, const int* in_sizes, int n_in,
                              void* d_out, int out_size) {
    const int*   idx    = (const int*)  d_in[0];
    const float* wte    = (const float*)d_in[1];
    const float* wpe    = (const float*)d_in[2];
    const float* ln1_s  = (const float*)d_in[3];
    const float* ln1_b  = (const float*)d_in[4];
    const float* qkv_w  = (const float*)d_in[5];
    const float* proj_w = (const float*)d_in[6];
    const float* ln2_s  = (const float*)d_in[7];
    const float* ln2_b  = (const float*)d_in[8];
    const float* fc_w   = (const float*)d_in[9];
    const float* fc_b   = (const float*)d_in[10];
    const float* fc2_w  = (const float*)d_in[11];
    const float* fc2_b  = (const float*)d_in[12];
    const float* lnf_s  = (const float*)d_in[13];
    const float* lnf_b  = (const float*)d_in[14];
    const float* lm_w   = (const float*)d_in[15];
    float* out = (float*)d_out;

    float *x, *h, *qkv, *y, *g;
    cudaGetSymbolAddress((void**)&x,   g_x);
    cudaGetSymbolAddress((void**)&h,   g_h);
    cudaGetSymbolAddress((void**)&qkv, g_qkv);
    cudaGetSymbolAddress((void**)&y,   g_y);
    cudaGetSymbolAddress((void**)&g,   g_g);

    embed_kernel<<<MM, 256>>>(idx, wte, wpe, x);

    for (int l = 0; l < LL; l++) {
        const float* qw  = qkv_w  + (size_t)l * 3 * DD * DD;
        const float* pw  = proj_w + (size_t)l * DD * DD;
        const float* fw  = fc_w   + (size_t)l * 4 * DD * DD;
        const float* fb  = fc_b   + (size_t)l * 4 * DD;
        const float* f2w = fc2_w  + (size_t)l * DD * 4 * DD;
        const float* f2b = fc2_b  + (size_t)l * DD;

        ln_kernel<<<MM, 256>>>(x, ln1_s + l * DD, ln1_b + l * DD, h);
        gemm_bf16s<<<dim3(3 * DD / BN, MM / BM), 256>>>(h, qw, nullptr, nullptr, qkv,
                                                        MM, 3 * DD, DD, 0);
        attn_kernel<<<dim3(TT / QB, HH, BB), QB * 32>>>(qkv, y);
        gemm_bf16s<<<dim3(DD / BN, MM / BM), 256>>>(y, pw, nullptr, x, x,
                                                    MM, DD, DD, FLAG_RES);
        ln_kernel<<<MM, 256>>>(x, ln2_s + l * DD, ln2_b + l * DD, h);
        gemm_bf16s<<<dim3(4 * DD / BN, MM / BM), 256>>>(h, fw, fb, nullptr, g,
                                                        MM, 4 * DD, DD, FLAG_BIAS | FLAG_GELU);
        gemm_bf16s<<<dim3(DD / BN, MM / BM), 256>>>(g, f2w, f2b, x, x,
                                                    MM, DD, 4 * DD, FLAG_BIAS | FLAG_RES);
    }

    ln_kernel<<<MM, 256>>>(x, lnf_s, lnf_b, h);
    gemm_bf16s<<<dim3(VV / BN, MM / BM), 256>>>(h, lm_w, nullptr, nullptr, out,
                                                MM, VV, DD, 0);
}

// round 4
// speedup vs baseline: 2.7088x; 1.2095x over previous
#include <cuda_runtime.h>
#include <cuda_bf16.h>
#include <math.h>
#include <stdint.h>

// Model dims
#define BB   2
#define TT   1024
#define DD   1024
#define HH   16
#define HDIM 64
#define LL   8
#define VV   32000
#define MM   (BB*TT)   // 2048 tokens

// GEMM tiling
#define BM 128
#define BN 128
#define BK 32
#define LDP 40           // smem row stride in bf16 (pad 32 -> 40)
#define BUFSZ (4*BM*LDP) // bf16 elems per pipeline buffer

typedef __nv_bfloat16 bf16;
typedef __nv_bfloat162 bf162;

// fp32 scratch
__device__ float g_x  [MM * DD];
__device__ float g_qkv[MM * 3 * DD];
// bf16 hi/lo activation scratch
__device__ bf16 g_h_hi[MM * DD],     g_h_lo[MM * DD];
__device__ bf16 g_y_hi[MM * DD],     g_y_lo[MM * DD];
__device__ bf16 g_g_hi[MM * 4 * DD], g_g_lo[MM * 4 * DD];
// bf16 hi/lo weight scratch
__device__ bf16 g_qkvw_hi[LL * 3 * DD * DD], g_qkvw_lo[LL * 3 * DD * DD];
__device__ bf16 g_projw_hi[LL * DD * DD],    g_projw_lo[LL * DD * DD];
__device__ bf16 g_fcw_hi [LL * 4 * DD * DD], g_fcw_lo [LL * 4 * DD * DD];
__device__ bf16 g_fc2w_hi[LL * 4 * DD * DD], g_fc2w_lo[LL * 4 * DD * DD];
__device__ bf16 g_lmw_hi [VV * DD],          g_lmw_lo [VV * DD];

// ---------------------------------------------------------------------------
// Elementwise fp32 -> (hi, lo) bf16 split
// ---------------------------------------------------------------------------
__global__ void wsplit_kernel(const float* __restrict__ src,
                              bf16* __restrict__ hi, bf16* __restrict__ lo, int n) {
    int i = (blockIdx.x * blockDim.x + threadIdx.x) * 4;
    if (i >= n) return;
    float4 v = *(const float4*)(src + i);
    bf16 h0 = __float2bfloat16(v.x), h1 = __float2bfloat16(v.y);
    bf16 h2 = __float2bfloat16(v.z), h3 = __float2bfloat16(v.w);
    bf162 hp0; hp0.x = h0; hp0.y = h1;
    bf162 hp1; hp1.x = h2; hp1.y = h3;
    bf162 lp0; lp0.x = __float2bfloat16(v.x - __bfloat162float(h0));
               lp0.y = __float2bfloat16(v.y - __bfloat162float(h1));
    bf162 lp1; lp1.x = __float2bfloat16(v.z - __bfloat162float(h2));
               lp1.y = __float2bfloat16(v.w - __bfloat162float(h3));
    ((bf162*)(hi + i))[0] = hp0; ((bf162*)(hi + i))[1] = hp1;
    ((bf162*)(lo + i))[0] = lp0; ((bf162*)(lo + i))[1] = lp1;
}

// ---------------------------------------------------------------------------
// Embedding
// ---------------------------------------------------------------------------
__global__ void embed_kernel(const int* __restrict__ idx,
                             const float* __restrict__ wte,
                             const float* __restrict__ wpe,
                             float* __restrict__ x) {
    int token = blockIdx.x;
    int t = token % TT;
    int id = idx[token];
    const float4* src = (const float4*)(wte + (size_t)id * DD);
    const float4* pos = (const float4*)(wpe + (size_t)t * DD);
    float4* dst = (float4*)(x + (size_t)token * DD);
    for (int i = threadIdx.x; i < DD / 4; i += blockDim.x) {
        float4 a = src[i], b = pos[i];
        dst[i] = make_float4(a.x + b.x, a.y + b.y, a.z + b.z, a.w + b.w);
    }
}

// ---------------------------------------------------------------------------
// LayerNorm over D=1024, writing bf16 hi/lo split output
// ---------------------------------------------------------------------------
__global__ __launch_bounds__(256) void ln_split_kernel(const float* __restrict__ x,
                                                       const float* __restrict__ sc,
                                                       const float* __restrict__ bi,
                                                       bf16* __restrict__ ohi,
                                                       bf16* __restrict__ olo) {
    int token = blockIdx.x;
    const float4* xp = (const float4*)(x + (size_t)token * DD);
    float4 v = xp[threadIdx.x];
    float s = v.x + v.y + v.z + v.w;
    float q = v.x * v.x + v.y * v.y + v.z * v.z + v.w * v.w;
#pragma unroll
    for (int o = 16; o; o >>= 1) {
        s += __shfl_xor_sync(0xffffffffu, s, o);
        q += __shfl_xor_sync(0xffffffffu, q, o);
    }
    __shared__ float ss[8], sq[8];
    int w = threadIdx.x >> 5, l = threadIdx.x & 31;
    if (l == 0) { ss[w] = s; sq[w] = q; }
    __syncthreads();
    if (w == 0) {
        s = (l < 8) ? ss[l] : 0.f;
        q = (l < 8) ? sq[l] : 0.f;
#pragma unroll
        for (int o = 4; o; o >>= 1) {
            s += __shfl_xor_sync(0xffffffffu, s, o);
            q += __shfl_xor_sync(0xffffffffu, q, o);
        }
        if (l == 0) { ss[0] = s; sq[0] = q; }
    }
    __syncthreads();
    float mu  = ss[0] * (1.f / DD);
    float var = sq[0] * (1.f / DD) - mu * mu;
    float inv = rsqrtf(var + 1e-5f);
    float4 sv = ((const float4*)sc)[threadIdx.x];
    float4 bv = ((const float4*)bi)[threadIdx.x];
    float r0 = (v.x - mu) * inv * sv.x + bv.x;
    float r1 = (v.y - mu) * inv * sv.y + bv.y;
    float r2 = (v.z - mu) * inv * sv.z + bv.z;
    float r3 = (v.w - mu) * inv * sv.w + bv.w;
    size_t o = (size_t)token * DD + threadIdx.x * 4;
    bf16 h0 = __float2bfloat16(r0), h1 = __float2bfloat16(r1);
    bf16 h2 = __float2bfloat16(r2), h3 = __float2bfloat16(r3);
    bf162 p;
    p.x = h0; p.y = h1; ((bf162*)(ohi + o))[0] = p;
    p.x = h2; p.y = h3; ((bf162*)(ohi + o))[1] = p;
    p.x = __float2bfloat16(r0 - __bfloat162float(h0));
    p.y = __float2bfloat16(r1 - __bfloat162float(h1));
    ((bf162*)(olo + o))[0] = p;
    p.x = __float2bfloat16(r2 - __bfloat162float(h2));
    p.y = __float2bfloat16(r3 - __bfloat162float(h3));
    ((bf162*)(olo + o))[1] = p;
}

// ---------------------------------------------------------------------------
// Tensor-core GEMM NT, 3-pass bf16-split operands pre-split in HBM.
// cp.async double-buffered. C[m,n] = sum_k A[m,k]*B[n,k].
// ---------------------------------------------------------------------------
#define FLAG_BIAS  1
#define FLAG_RES   2
#define FLAG_GELU  4
#define FLAG_SPLIT 8

__device__ __forceinline__ float gelu_exact(float v) {
    return 0.5f * v * (1.f + erff(v * 0.70710678118654752f));
}

__device__ __forceinline__ void ldm_x4(uint32_t& r0, uint32_t& r1, uint32_t& r2, uint32_t& r3,
                                       uint32_t addr) {
    asm volatile("ldmatrix.sync.aligned.m8n8.x4.shared.b16 {%0,%1,%2,%3}, [%4];\n"
                 : "=r"(r0), "=r"(r1), "=r"(r2), "=r"(r3) : "r"(addr));
}

__device__ __forceinline__ void mma16816(float* d, const uint32_t* a, const uint32_t* b) {
    asm volatile(
        "mma.sync.aligned.m16n8k16.row.col.f32.bf16.bf16.f32 "
        "{%0,%1,%2,%3}, {%4,%5,%6,%7}, {%8,%9}, {%0,%1,%2,%3};\n"
        : "+f"(d[0]), "+f"(d[1]), "+f"(d[2]), "+f"(d[3])
        : "r"(a[0]), "r"(a[1]), "r"(a[2]), "r"(a[3]), "r"(b[0]), "r"(b[1]));
}

__device__ __forceinline__ void cp16(uint32_t dst, const void* src) {
    asm volatile("cp.async.cg.shared.global [%0], [%1], 16;\n" :: "r"(dst), "l"(src));
}

__global__ __launch_bounds__(256) void gemm3(const bf16* __restrict__ Ah,
                                             const bf16* __restrict__ Al,
                                             const bf16* __restrict__ Bh,
                                             const bf16* __restrict__ Bl,
                                             const float* __restrict__ bias,
                                             const float* res,
                                             float* C, bf16* Chi, bf16* Clo,
                                             int M, int N, int K, int flags) {
    extern __shared__ __align__(16) bf16 sm[];   // [2][4][BM*LDP]

    int tid = threadIdx.x;
    int warp = tid >> 5, lane = tid & 31;
    int bm = blockIdx.y * BM, bn = blockIdx.x * BN;
    int wm = (warp >> 2) * 64;
    int wn = (warp & 3) * 32;

    uint32_t smbase = (uint32_t)__cvta_generic_to_shared(sm);

    float acc[4][4][4];
#pragma unroll
    for (int i = 0; i < 4; i++)
#pragma unroll
        for (int j = 0; j < 4; j++)
#pragma unroll
            for (int r = 0; r < 4; r++) acc[i][j][r] = 0.f;

    // ldmatrix lane addressing
    int a_r = ((lane >> 3) & 1) * 8 + (lane & 7);
    int a_c = (lane >> 4) * 8;
    int b_r = (lane >> 4) * 8 + (lane & 7);
    int b_c = ((lane >> 3) & 1) * 8;

    const bf16* srcs[4] = { Ah, Al, Bh, Bl };
    int rowbase[4] = { bm, bm, bn, bn };

    // stage: issue cp.async for one buffer covering 4 arrays x 128 rows x 32 bf16
    auto stage = [&](int buf, int k0) {
#pragma unroll
        for (int i = 0; i < 8; i++) {
            int arr = i >> 1;
            int c = tid + (i & 1) * 256;      // 0..511
            int row = c >> 2;
            int col = (c & 3) * 8;
            const bf16* src = srcs[arr] + (size_t)(rowbase[arr] + row) * K + k0 + col;
            uint32_t dst = smbase + (uint32_t)(buf * BUFSZ + arr * (BM * LDP) + row * LDP + col) * 2;
            cp16(dst, src);
        }
        asm volatile("cp.async.commit_group;\n");
    };

    stage(0, 0);
    int buf = 0;
    for (int k0 = 0; k0 < K; k0 += BK) {
        if (k0 + BK < K) {
            stage(buf ^ 1, k0 + BK);
            asm volatile("cp.async.wait_group 1;\n");
        } else {
            asm volatile("cp.async.wait_group 0;\n");
        }
        __syncthreads();

        uint32_t offAh = smbase + (uint32_t)(buf * BUFSZ) * 2;
        uint32_t offAl = offAh + (uint32_t)(BM * LDP) * 2;
        uint32_t offBh = offAl + (uint32_t)(BM * LDP) * 2;
        uint32_t offBl = offBh + (uint32_t)(BM * LDP) * 2;

#pragma unroll
        for (int ks = 0; ks < BK; ks += 16) {
            uint32_t ah[4][4], al[4][4], bh[4][2], bl[4][2];
#pragma unroll
            for (int mf = 0; mf < 4; mf++) {
                uint32_t addr = offAh + (uint32_t)((wm + mf * 16 + a_r) * LDP + ks + a_c) * 2;
                ldm_x4(ah[mf][0], ah[mf][1], ah[mf][2], ah[mf][3], addr);
            }
#pragma unroll
            for (int p = 0; p < 2; p++) {
                uint32_t addr = offBh + (uint32_t)((wn + p * 16 + b_r) * LDP + ks + b_c) * 2;
                uint32_t r0, r1, r2, r3;
                ldm_x4(r0, r1, r2, r3, addr);
                bh[2 * p][0] = r0; bh[2 * p][1] = r1;
                bh[2 * p + 1][0] = r2; bh[2 * p + 1][1] = r3;
            }
#pragma unroll
            for (int mf = 0; mf < 4; mf++)
#pragma unroll
                for (int nf = 0; nf < 4; nf++)
                    mma16816(acc[mf][nf], ah[mf], bh[nf]);

#pragma unroll
            for (int p = 0; p < 2; p++) {
                uint32_t addr = offBl + (uint32_t)((wn + p * 16 + b_r) * LDP + ks + b_c) * 2;
                uint32_t r0, r1, r2, r3;
                ldm_x4(r0, r1, r2, r3, addr);
                bl[2 * p][0] = r0; bl[2 * p][1] = r1;
                bl[2 * p + 1][0] = r2; bl[2 * p + 1][1] = r3;
            }
#pragma unroll
            for (int mf = 0; mf < 4; mf++)
#pragma unroll
                for (int nf = 0; nf < 4; nf++)
                    mma16816(acc[mf][nf], ah[mf], bl[nf]);

#pragma unroll
            for (int mf = 0; mf < 4; mf++) {
                uint32_t addr = offAl + (uint32_t)((wm + mf * 16 + a_r) * LDP + ks + a_c) * 2;
                ldm_x4(al[mf][0], al[mf][1], al[mf][2], al[mf][3], addr);
            }
#pragma unroll
            for (int mf = 0; mf < 4; mf++)
#pragma unroll
                for (int nf = 0; nf < 4; nf++)
                    mma16816(acc[mf][nf], al[mf], bh[nf]);
        }
        __syncthreads();
        buf ^= 1;
    }

    // epilogue
    int gid = lane >> 2, tg = lane & 3;
#pragma unroll
    for (int mf = 0; mf < 4; mf++) {
#pragma unroll
        for (int half = 0; half < 2; half++) {
            int row = bm + wm + mf * 16 + half * 8 + gid;
#pragma unroll
            for (int nf = 0; nf < 4; nf++) {
                int col = bn + wn + nf * 8 + tg * 2;
                float2 o;
                o.x = acc[mf][nf][half * 2 + 0];
                o.y = acc[mf][nf][half * 2 + 1];
                if (flags & FLAG_BIAS) { o.x += bias[col]; o.y += bias[col + 1]; }
                if (flags & FLAG_GELU) { o.x = gelu_exact(o.x); o.y = gelu_exact(o.y); }
                if (flags & FLAG_RES) {
                    float2 r = *(const float2*)(res + (size_t)row * N + col);
                    o.x += r.x; o.y += r.y;
                }
                if (flags & FLAG_SPLIT) {
                    size_t off = (size_t)row * N + col;
                    bf16 h0 = __float2bfloat16(o.x), h1 = __float2bfloat16(o.y);
                    bf162 hp; hp.x = h0; hp.y = h1;
                    *(bf162*)(Chi + off) = hp;
                    bf162 lp;
                    lp.x = __float2bfloat16(o.x - __bfloat162float(h0));
                    lp.y = __float2bfloat16(o.y - __bfloat162float(h1));
                    *(bf162*)(Clo + off) = lp;
                } else {
                    *(float2*)(C + (size_t)row * N + col) = o;
                }
            }
        }
    }
}

// ---------------------------------------------------------------------------
// Causal attention (flash-style). 64 queries/block, 8 warps, 8 queries/warp.
// Lane = key for scores; PV via shfl transpose. Writes y as bf16 hi/lo.
// ---------------------------------------------------------------------------
__global__ __launch_bounds__(256) void attn_kernel(const float* __restrict__ qkv,
                                                   bf16* __restrict__ yhi,
                                                   bf16* __restrict__ ylo) {
    int b = blockIdx.z, h = blockIdx.y, bx = blockIdx.x;
    int tid = threadIdx.x;
    int warp = tid >> 5, lane = tid & 31;
    int q0g = bx * 64 + warp * 8;          // first global query of this warp
    int w8 = warp * 8;                     // local q_s row base

    __shared__ float q_s[64][66];
    __shared__ float k_s[32][66];
    __shared__ float v_s[32][66];

    // load Q (scaled by 1/sqrt(64))
#pragma unroll
    for (int i = 0; i < 8; i++) {
        int cid = tid + i * 256;
        int row = cid >> 5, c2 = cid & 31;
        const float* qp = qkv + (size_t)(b * TT + bx * 64 + row) * (3 * DD) + h * HDIM;
        float2 qv = *(const float2*)(qp + c2 * 2);
        q_s[row][c2 * 2]     = qv.x * 0.125f;
        q_s[row][c2 * 2 + 1] = qv.y * 0.125f;
    }

    float m[8], l[8], accx[8], accy[8];
#pragma unroll
    for (int q = 0; q < 8; q++) { m[q] = -INFINITY; l[q] = 0.f; accx[q] = 0.f; accy[q] = 0.f; }

    int ntiles = bx * 2 + 2;
    const float* kb = qkv + (size_t)(b * TT) * (3 * DD) + DD + h * HDIM;
    const float* vb = kb + DD;

    for (int tile = 0; tile < ntiles; tile++) {
        int kt = tile * 32;
        __syncthreads();
#pragma unroll
        for (int i = 0; i < 8; i++) {
            int cid = tid + i * 256;
            int which = cid >> 10, r = (cid >> 5) & 31, c2 = cid & 31;
            const float* src = (which ? vb : kb) + (size_t)(kt + r) * (3 * DD) + c2 * 2;
            float2 v2 = *(const float2*)src;
            if (which) { v_s[r][c2 * 2] = v2.x; v_s[r][c2 * 2 + 1] = v2.y; }
            else       { k_s[r][c2 * 2] = v2.x; k_s[r][c2 * 2 + 1] = v2.y; }
        }
        __syncthreads();

        if (kt <= q0g + 7) {
            float s[8];
#pragma unroll
            for (int q = 0; q < 8; q++) s[q] = 0.f;
#pragma unroll
            for (int d2 = 0; d2 < 32; d2++) {
                float2 kk = *(const float2*)&k_s[lane][d2 * 2];
#pragma unroll
                for (int q = 0; q < 8; q++) {
                    float2 qq = *(const float2*)&q_s[w8 + q][d2 * 2];
                    s[q] = fmaf(qq.x, kk.x, s[q]);
                    s[q] = fmaf(qq.y, kk.y, s[q]);
                }
            }
            int key = kt + lane;
#pragma unroll
            for (int q = 0; q < 8; q++) {
                if (key > q0g + q) s[q] = -INFINITY;
                float tm = s[q];
#pragma unroll
                for (int o = 16; o; o >>= 1) tm = fmaxf(tm, __shfl_xor_sync(0xffffffffu, tm, o));
                float mn = fmaxf(m[q], tm);
                float corr = __expf(m[q] - mn);
                float p = __expf(s[q] - mn);
                float ps = p;
#pragma unroll
                for (int o = 16; o; o >>= 1) ps += __shfl_xor_sync(0xffffffffu, ps, o);
                l[q] = l[q] * corr + ps;
                accx[q] *= corr; accy[q] *= corr;
                m[q] = mn;
                s[q] = p;                 // reuse as probability
            }
#pragma unroll
            for (int j = 0; j < 32; j++) {
                float2 vv = *(const float2*)&v_s[j][lane * 2];
#pragma unroll
                for (int q = 0; q < 8; q++) {
                    float pj = __shfl_sync(0xffffffffu, s[q], j);
                    accx[q] = fmaf(pj, vv.x, accx[q]);
                    accy[q] = fmaf(pj, vv.y, accy[q]);
                }
            }
        }
    }

#pragma unroll
    for (int q = 0; q < 8; q++) {
        float inv = 1.f / l[q];
        float ox = accx[q] * inv, oy = accy[q] * inv;
        size_t off = (size_t)(b * TT + q0g + q) * DD + h * HDIM + lane * 2;
        bf16 h0 = __float2bfloat16(ox), h1 = __float2bfloat16(oy);
        bf162 hp; hp.x = h0; hp.y = h1;
        *(bf162*)(yhi + off) = hp;
        bf162 lp;
        lp.x = __float2bfloat16(ox - __bfloat162float(h0));
        lp.y = __float2bfloat16(oy - __bfloat162float(h1));
        *(bf162*)(ylo + off) = lp;
    }
}

// ---------------------------------------------------------------------------
// Host launcher
// ---------------------------------------------------------------------------
extern "C" void kernel_launch(void* const* d_in, const int* in_sizes, int n_in,
                              void* d_out, int out_size) {
    const int*   idx    = (const int*)  d_in[0];
    const float* wte    = (const float*)d_in[1];
    const float* wpe    = (const float*)d_in[2];
    const float* ln1_s  = (const float*)d_in[3];
    const float* ln1_b  = (const float*)d_in[4];
    const float* qkv_w  = (const float*)d_in[5];
    const float* proj_w = (const float*)d_in[6];
    const float* ln2_s  = (const float*)d_in[7];
    const float* ln2_b  = (const float*)d_in[8];
    const float* fc_w   = (const float*)d_in[9];
    const float* fc_b   = (const float*)d_in[10];
    const float* fc2_w  = (const float*)d_in[11];
    const float* fc2_b  = (const float*)d_in[12];
    const float* lnf_s  = (const float*)d_in[13];
    const float* lnf_b  = (const float*)d_in[14];
    const float* lm_w   = (const float*)d_in[15];
    float* out = (float*)d_out;

    float *x, *qkv;
    bf16 *h_hi, *h_lo, *y_hi, *y_lo, *gg_hi, *gg_lo;
    bf16 *qw_hi, *qw_lo, *pw_hi, *pw_lo, *fw_hi, *fw_lo, *f2_hi, *f2_lo, *lw_hi, *lw_lo;
    cudaGetSymbolAddress((void**)&x,     g_x);
    cudaGetSymbolAddress((void**)&qkv,   g_qkv);
    cudaGetSymbolAddress((void**)&h_hi,  g_h_hi);   cudaGetSymbolAddress((void**)&h_lo,  g_h_lo);
    cudaGetSymbolAddress((void**)&y_hi,  g_y_hi);   cudaGetSymbolAddress((void**)&y_lo,  g_y_lo);
    cudaGetSymbolAddress((void**)&gg_hi, g_g_hi);   cudaGetSymbolAddress((void**)&gg_lo, g_g_lo);
    cudaGetSymbolAddress((void**)&qw_hi, g_qkvw_hi); cudaGetSymbolAddress((void**)&qw_lo, g_qkvw_lo);
    cudaGetSymbolAddress((void**)&pw_hi, g_projw_hi); cudaGetSymbolAddress((void**)&pw_lo, g_projw_lo);
    cudaGetSymbolAddress((void**)&fw_hi, g_fcw_hi);  cudaGetSymbolAddress((void**)&fw_lo, g_fcw_lo);
    cudaGetSymbolAddress((void**)&f2_hi, g_fc2w_hi); cudaGetSymbolAddress((void**)&f2_lo, g_fc2w_lo);
    cudaGetSymbolAddress((void**)&lw_hi, g_lmw_hi);  cudaGetSymbolAddress((void**)&lw_lo, g_lmw_lo);

    static bool smem_set = false;
    cudaFuncSetAttribute(gemm3, cudaFuncAttributeMaxDynamicSharedMemorySize, 2 * BUFSZ * 2);
    (void)smem_set;
    const int GSM = 2 * BUFSZ * 2;  // 81920 bytes

    // split all weights (once per forward)
    {
        int n;
        n = LL * 3 * DD * DD; wsplit_kernel<<<n / 1024, 256>>>(qkv_w,  qw_hi, qw_lo, n);
        n = LL * DD * DD;     wsplit_kernel<<<n / 1024, 256>>>(proj_w, pw_hi, pw_lo, n);
        n = LL * 4 * DD * DD; wsplit_kernel<<<n / 1024, 256>>>(fc_w,   fw_hi, fw_lo, n);
        n = LL * 4 * DD * DD; wsplit_kernel<<<n / 1024, 256>>>(fc2_w,  f2_hi, f2_lo, n);
        n = VV * DD;          wsplit_kernel<<<n / 1024, 256>>>(lm_w,   lw_hi, lw_lo, n);
    }

    embed_kernel<<<MM, 256>>>(idx, wte, wpe, x);

    for (int l = 0; l < LL; l++) {
        bf16* qwh = qw_hi + (size_t)l * 3 * DD * DD;  bf16* qwl = qw_lo + (size_t)l * 3 * DD * DD;
        bf16* pwh = pw_hi + (size_t)l * DD * DD;      bf16* pwl = pw_lo + (size_t)l * DD * DD;
        bf16* fwh = fw_hi + (size_t)l * 4 * DD * DD;  bf16* fwl = fw_lo + (size_t)l * 4 * DD * DD;
        bf16* f2h = f2_hi + (size_t)l * 4 * DD * DD;  bf16* f2l = f2_lo + (size_t)l * 4 * DD * DD;
        const float* fb  = fc_b  + (size_t)l * 4 * DD;
        const float* f2b = fc2_b + (size_t)l * DD;

        ln_split_kernel<<<MM, 256>>>(x, ln1_s + l * DD, ln1_b + l * DD, h_hi, h_lo);
        gemm3<<<dim3(3 * DD / BN, MM / BM), 256, GSM>>>(h_hi, h_lo, qwh, qwl,
            nullptr, nullptr, qkv, nullptr, nullptr, MM, 3 * DD, DD, 0);
        attn_kernel<<<dim3(TT / 64, HH, BB), 256>>>(qkv, y_hi, y_lo);
        gemm3<<<dim3(DD / BN, MM / BM), 256, GSM>>>(y_hi, y_lo, pwh, pwl,
            nullptr, x, x, nullptr, nullptr, MM, DD, DD, FLAG_RES);
        ln_split_kernel<<<MM, 256>>>(x, ln2_s + l * DD, ln2_b + l * DD, h_hi, h_lo);
        gemm3<<<dim3(4 * DD / BN, MM / BM), 256, GSM>>>(h_hi, h_lo, fwh, fwl,
            fb, nullptr, nullptr, gg_hi, gg_lo, MM, 4 * DD, DD, FLAG_BIAS | FLAG_GELU | FLAG_SPLIT);
        gemm3<<<dim3(DD / BN, MM / BM), 256, GSM>>>(gg_hi, gg_lo, f2h, f2l,
            f2b, x, x, nullptr, nullptr, MM, DD, 4 * DD, FLAG_BIAS | FLAG_RES);
    }

    ln_split_kernel<<<MM, 256>>>(x, lnf_s, lnf_b, h_hi, h_lo);
    gemm3<<<dim3(VV / BN, MM / BM), 256, GSM>>>(h_hi, h_lo, lw_hi, lw_lo,
        nullptr, nullptr, out, nullptr, nullptr, MM, VV, DD, 0);
}